// round 12
// baseline (speedup 1.0000x reference)
#include <cuda_runtime.h>
#include <math.h>
#include <stdint.h>

// Shapes (fixed): U=256, D=5120, N=16, R=160
#define U_DIM 256
#define D_DIM 5120
#define N_DIM 16
#define R_DIM 160
#define NCOL  176   // 160 (t) + 16 (B)
#define NPAD  192   // padded col space: 3 col-pairs x 32 lanes

typedef unsigned long long ull;

// ---------------- scratch ----------------
#define S1_SPLITS 32
#define S1_KC     160     // K per split = 5 stages of 32
#define S1_KK     32      // K per smem stage
#define S1_NST    (S1_KC / S1_KK)   // 5
#define S1_UT     64      // users per block
#define S1_THREADS 512
#define XPITCH    66      // xsh pitch in ull (even -> 16B-aligned v2 reads)

__device__ float g_partial[S1_SPLITS * U_DIM * NCOL];   // 5.8 MB
__device__ float g_tbuf[U_DIM * NCOL];                  // t | B

// ---------------- helpers ----------------
__device__ __forceinline__ ull pack2(float v) {
    ull r; asm("mov.b64 %0, {%1, %1};" : "=l"(r) : "f"(v)); return r;
}
__device__ __forceinline__ ull combine2(float lo, float hi) {
    ull r; asm("mov.b64 %0, {%1, %2};" : "=l"(r) : "f"(lo), "f"(hi)); return r;
}
__device__ __forceinline__ void fma2(ull& acc, ull a, ull b) {
    asm("fma.rn.f32x2 %0, %1, %2, %0;" : "+l"(acc) : "l"(a), "l"(b));
}
__device__ __forceinline__ void lds_v2b64(ull& a, ull& b, uint32_t addr) {
    asm volatile("ld.shared.v2.b64 {%0, %1}, [%2];" : "=l"(a), "=l"(b) : "r"(addr));
}
__device__ __forceinline__ ull lds_b64(uint32_t addr) {
    ull a; asm volatile("ld.shared.b64 %0, [%1];" : "=l"(a) : "r"(addr)); return a;
}
__device__ __forceinline__ void cp16(uint32_t dst, const void* src) {
    asm volatile("cp.async.ca.shared.global [%0], [%1], 16;" :: "r"(dst), "l"(src));
}
__device__ __forceinline__ void cp_commit() { asm volatile("cp.async.commit_group;"); }
__device__ __forceinline__ void cp_wait0()  { asm volatile("cp.async.wait_group 0;"); }
__device__ __forceinline__ void cp_wait1()  { asm volatile("cp.async.wait_group 1;"); }
__device__ __forceinline__ void cp_wait2()  { asm volatile("cp.async.wait_group 2;"); }

// ================= Stage 1: split-K GEMM  t_ext[U,176] = x @ [W1 | Bp] ==========
// (exact R8 winner: 512 threads, KC=160, 5 stages of 32, warp owns 4 users)
__global__ void __launch_bounds__(S1_THREADS) stage1_kernel(
    const float* __restrict__ x,
    const float* __restrict__ W1,   // [5120,160]
    const float* __restrict__ Bp)   // [5120,16]
{
    __shared__ __align__(16) ull   xsh[2][S1_KK * XPITCH];    // {x,x} dup, 2x16.9KB
    __shared__ __align__(16) float wsh[2][S1_KK * NPAD];      // [k][col], 2x24.6KB

    const int tid = threadIdx.x;
    const int cx  = tid & 31;
    const int wid = tid >> 5;        // 0..15
    const int u0  = blockIdx.x * S1_UT;
    const int k0  = blockIdx.y * S1_KC;

    const uint32_t xb = (uint32_t)__cvta_generic_to_shared(xsh);
    const uint32_t wb = (uint32_t)__cvta_generic_to_shared(wsh);

    const int xu = tid >> 5;         // 0..15 base user
    const int xk = tid & 31;         // lane -> k within stage

    auto stage_w = [&](int s, int b) {
        const int kb = k0 + s * S1_KK;
        const uint32_t wdst = wb + (uint32_t)(b * S1_KK * NPAD) * 4u;
        for (int ch = tid; ch < S1_KK * 40; ch += S1_THREADS) {
            int k = ch / 40, c = ch - k * 40;
            cp16(wdst + (uint32_t)(k * NPAD + c * 4) * 4u,
                 W1 + (size_t)(kb + k) * R_DIM + c * 4);
        }
        if (tid < S1_KK * 4) {
            int k = tid >> 2, c = tid & 3;
            cp16(wdst + (uint32_t)(k * NPAD + R_DIM + c * 4) * 4u,
                 Bp + (size_t)(kb + k) * N_DIM + c * 4);
        }
        cp_commit();
    };
    float xr[4];
    auto load_x = [&](int s) {
#pragma unroll
        for (int j = 0; j < 4; ++j) {
            int u = xu + j * 16;
            xr[j] = x[(size_t)(u0 + u) * D_DIM + k0 + s * S1_KK + xk];
        }
    };
    auto sts_x = [&](int b) {
#pragma unroll
        for (int j = 0; j < 4; ++j)
            xsh[b][xk * XPITCH + xu + j * 16] = pack2(xr[j]);
    };

    ull acc[4][3];
#pragma unroll
    for (int uu = 0; uu < 4; ++uu)
#pragma unroll
        for (int c = 0; c < 3; ++c) acc[uu][c] = 0ULL;

    stage_w(0, 0);
    load_x(0);

#pragma unroll 1
    for (int s = 0; s < S1_NST; ++s) {
        const int b = s & 1;
        sts_x(b);
        if (s + 1 < S1_NST) stage_w(s + 1, 1 - b);
        if (s + 1 < S1_NST) cp_wait1(); else cp_wait0();
        __syncthreads();
        if (s + 1 < S1_NST) load_x(s + 1);

        const uint32_t xbase = xb + (uint32_t)(b * S1_KK * XPITCH) * 8u;
        const uint32_t wbase = wb + (uint32_t)(b * S1_KK * NPAD) * 4u;
#pragma unroll 4
        for (int kk = 0; kk < S1_KK; ++kk) {
            ull xp[4];
            const uint32_t xa = xbase + (uint32_t)(kk * XPITCH + wid * 4) * 8u;
            lds_v2b64(xp[0], xp[1], xa);
            lds_v2b64(xp[2], xp[3], xa + 16u);
            const uint32_t wa = wbase + (uint32_t)(kk * NPAD + 2 * cx) * 4u;
            ull wp[3];
            wp[0] = lds_b64(wa);
            wp[1] = lds_b64(wa + 256u);
            wp[2] = lds_b64(wa + 512u);
#pragma unroll
            for (int c = 0; c < 3; ++c)
#pragma unroll
                for (int uu = 0; uu < 4; ++uu) fma2(acc[uu][c], xp[uu], wp[c]);
        }
        __syncthreads();
    }

    float* pout = g_partial + (size_t)blockIdx.y * (U_DIM * NCOL);
#pragma unroll
    for (int uu = 0; uu < 4; ++uu) {
        const int u = u0 + wid * 4 + uu;
#pragma unroll
        for (int c = 0; c < 3; ++c) {
            if (c < 2 || cx < 24) {
                const int col = 64 * c + 2 * cx;
                *(ull*)(pout + (size_t)u * NCOL + col) = acc[uu][c];
            }
        }
    }
}

// ================= Stage 2: reduce 32 split partials (float4) ===================
#define RED_F4 (U_DIM * NCOL / 4)   // 11264
__global__ void __launch_bounds__(256) reduce_kernel() {
    const int idx = blockIdx.x * 256 + threadIdx.x;   // 44 * 256 == 11264 exactly
    const float4* p4 = (const float4*)g_partial;
    float4 s = make_float4(0.f, 0.f, 0.f, 0.f);
#pragma unroll
    for (int sp = 0; sp < S1_SPLITS; ++sp) {
        float4 v = __ldcg(p4 + (size_t)sp * RED_F4 + idx);
        s.x += v.x; s.y += v.y; s.z += v.z; s.w += v.w;
    }
    ((float4*)g_tbuf)[idx] = s;
}

// ================= Stage 3: fused dt-GEMM + softplus + streaming ================
// Block: 8 users x 128 d. W2 via 4-deep cp.async ring (3 chunks in flight).
#define FU_UT 8
#define FU_DT 128
#define RCH 16                 // r rows per chunk
#define NCH (R_DIM / RCH)      // 10 chunks
#define W2CHUNK (RCH * FU_DT)  // floats per chunk (2048)

__global__ void __launch_bounds__(256, 5) fused_kernel(
    const float* __restrict__ W2,    // [160,5120]
    const float* __restrict__ bias,  // [5120]
    const float* __restrict__ x,     // [256,5120]
    const float4* __restrict__ abar4,
    const float4* __restrict__ hst4,
    float4* __restrict__ out4)
{
    __shared__ __align__(16) ull   tpair[R_DIM * 4];          // {t_u,t_u+1} 5.1 KB
    __shared__ __align__(16) float w2sh[4 * W2CHUNK];         // 32 KB ring
    __shared__ __align__(16) float c1sh[FU_UT * FU_DT];       // 4 KB
    __shared__ __align__(16) float Bsh[FU_UT * N_DIM];        // 0.5 KB

    const int u0  = blockIdx.x * FU_UT;
    const int d0  = blockIdx.y * FU_DT;
    const int tid = threadIdx.x;

    const uint32_t w2b = (uint32_t)__cvta_generic_to_shared(w2sh);
    const uint32_t tpb = (uint32_t)__cvta_generic_to_shared(tpair);

    auto issue_chunk = [&](int s) {
        const uint32_t dst = w2b + (uint32_t)((s & 3) * W2CHUNK) * 4u;
#pragma unroll
        for (int q = 0; q < 2; ++q) {
            int ch = tid + q * 256;
            int row = ch >> 5, c = ch & 31;
            cp16(dst + (uint32_t)(row * FU_DT + c * 4) * 4u,
                 W2 + (size_t)(s * RCH + row) * D_DIM + d0 + c * 4);
        }
        cp_commit();
    };

    // prologue: 3 chunks in flight
    issue_chunk(0);
    issue_chunk(1);
    issue_chunk(2);

    // stage t as user-pairs (overlaps with cp.async)
    for (int e = tid; e < R_DIM * 4; e += 256) {
        int r = e >> 2, p = e & 3;
        float lo = g_tbuf[(size_t)(u0 + 2 * p)     * NCOL + r];
        float hi = g_tbuf[(size_t)(u0 + 2 * p + 1) * NCOL + r];
        tpair[r * 4 + p] = combine2(lo, hi);
    }
    if (tid < FU_UT * N_DIM) {
        int u = tid >> 4, n = tid & 15;
        Bsh[tid] = g_tbuf[(size_t)(u0 + u) * NCOL + R_DIM + n];
    }

    // ---- GEMM phase: 10 chunks of 16 r, 3-chunk lookahead ----
    const int dl = tid & 127;
    const int g  = tid >> 7;       // 0 or 1
    const int pg = g * 2;          // pair-group base
    const int d  = d0 + dl;

    ull acc[2];
    acc[0] = 0ULL; acc[1] = 0ULL;

#pragma unroll 1
    for (int s = 0; s < NCH; ++s) {
        // wait so that chunk s is complete: pending allowed = issued - (s+1)
        if (s < NCH - 2)      cp_wait2();
        else if (s == NCH - 2) cp_wait1();
        else                  cp_wait0();
        __syncthreads();   // all threads see chunk s; all done with buffer (s-1)&3
        if (s + 3 < NCH) issue_chunk(s + 3);

        const uint32_t wbase = w2b + (uint32_t)((s & 3) * W2CHUNK + dl) * 4u;
        const uint32_t tbase = tpb + (uint32_t)(s * RCH * 4 + pg) * 8u;
#pragma unroll
        for (int rr = 0; rr < RCH; ++rr) {
            float wv;
            asm volatile("ld.shared.b32 %0, [%1];"
                         : "=f"(wv) : "r"(wbase + (uint32_t)(rr * FU_DT) * 4u));
            const ull w2 = pack2(wv);
            ull p0, p1;
            lds_v2b64(p0, p1, tbase + (uint32_t)(rr * 4) * 8u);
            fma2(acc[0], p0, w2);
            fma2(acc[1], p1, w2);
        }
    }

    const float bz = bias[d];
    const int ug = g * 4;
#pragma unroll
    for (int i = 0; i < 2; ++i) {
        float z0, z1;
        asm("mov.b64 {%0, %1}, %2;" : "=f"(z0), "=f"(z1) : "l"(acc[i]));
        const int u = ug + 2 * i;
        z0 += bz; z1 += bz;
        const float dt0 = fmaxf(z0, 0.f) + log1pf(expf(-fabsf(z0)));
        const float dt1 = fmaxf(z1, 0.f) + log1pf(expf(-fabsf(z1)));
        c1sh[u * FU_DT + dl]       = dt0 * __ldg(x + (size_t)(u0 + u) * D_DIM + d);
        c1sh[(u + 1) * FU_DT + dl] = dt1 * __ldg(x + (size_t)(u0 + u + 1) * D_DIM + d);
    }
    __syncthreads();

    // ---- streaming phase ----
    const int n4 = tid & 3;
    const int i0 = tid;
    const int i1 = tid + 256;

#pragma unroll 2
    for (int u = 0; u < FU_UT; ++u) {
        const size_t base = ((size_t)(u0 + u) * D_DIM + d0) * 4;  // float4 units
        const float4 b = *(const float4*)(Bsh + u * N_DIM + n4 * 4);
        const float c0 = c1sh[u * FU_DT + (i0 >> 2)];
        const float c1 = c1sh[u * FU_DT + (i1 >> 2)];

        const float4 a0 = __ldcs(abar4 + base + i0);
        const float4 h0 = __ldcs(hst4  + base + i0);
        const float4 a1 = __ldcs(abar4 + base + i1);
        const float4 h1 = __ldcs(hst4  + base + i1);

        float4 o0, o1;
        o0.x = fmaf(a0.x, h0.x, c0 * b.x);
        o0.y = fmaf(a0.y, h0.y, c0 * b.y);
        o0.z = fmaf(a0.z, h0.z, c0 * b.z);
        o0.w = fmaf(a0.w, h0.w, c0 * b.w);
        o1.x = fmaf(a1.x, h1.x, c1 * b.x);
        o1.y = fmaf(a1.y, h1.y, c1 * b.y);
        o1.z = fmaf(a1.z, h1.z, c1 * b.z);
        o1.w = fmaf(a1.w, h1.w, c1 * b.w);
        __stcs(out4 + base + i0, o0);
        __stcs(out4 + base + i1, o1);
    }
}

extern "C" void kernel_launch(void* const* d_in, const int* in_sizes, int n_in,
                              void* d_out, int out_size) {
    const float* x    = (const float*)d_in[0];   // [256,5120]
    const float* W1   = (const float*)d_in[1];   // [5120,160]
    const float* W2   = (const float*)d_in[2];   // [160,5120]
    const float* bias = (const float*)d_in[3];   // [5120]
    const float* Bp   = (const float*)d_in[4];   // [5120,16]
    const float* abar = (const float*)d_in[5];   // [256,5120,16]
    const float* hst  = (const float*)d_in[6];   // [256,5120,16]
    float* out = (float*)d_out;

    stage1_kernel<<<dim3(U_DIM / S1_UT, S1_SPLITS), S1_THREADS>>>(x, W1, Bp);
    reduce_kernel<<<RED_F4 / 256, 256>>>();
    fused_kernel<<<dim3(U_DIM / FU_UT, D_DIM / FU_DT), 256>>>(
        W2, bias, x, (const float4*)abar, (const float4*)hst, (float4*)out);
}

// round 13
// speedup vs baseline: 1.0853x; 1.0853x over previous
#include <cuda_runtime.h>
#include <math.h>
#include <stdint.h>

// Shapes (fixed): U=256, D=5120, N=16, R=160
#define U_DIM 256
#define D_DIM 5120
#define N_DIM 16
#define R_DIM 160
#define NCOL  176   // 160 (t) + 16 (B)
#define NPAD  192   // padded col space: 3 col-pairs x 32 lanes

typedef unsigned long long ull;

// ---------------- scratch ----------------
#define S1_SPLITS 64
#define S1_KC     80      // K per split = 5 stages of 16
#define S1_KK     16      // K per smem stage
#define S1_NST    (S1_KC / S1_KK)   // 5
#define S1_UT     64      // users per block
#define S1_THREADS 512
#define XPITCH    66      // xsh pitch in ull (even -> 16B-aligned v2 reads)

__device__ float g_partial[S1_SPLITS * U_DIM * NCOL];   // 11.5 MB
__device__ float g_tbuf[U_DIM * NCOL];                  // t | B

// ---------------- helpers ----------------
__device__ __forceinline__ ull pack2(float v) {
    ull r; asm("mov.b64 %0, {%1, %1};" : "=l"(r) : "f"(v)); return r;
}
__device__ __forceinline__ ull combine2(float lo, float hi) {
    ull r; asm("mov.b64 %0, {%1, %2};" : "=l"(r) : "f"(lo), "f"(hi)); return r;
}
__device__ __forceinline__ void fma2(ull& acc, ull a, ull b) {
    asm("fma.rn.f32x2 %0, %1, %2, %0;" : "+l"(acc) : "l"(a), "l"(b));
}
__device__ __forceinline__ void lds_v2b64(ull& a, ull& b, uint32_t addr) {
    asm volatile("ld.shared.v2.b64 {%0, %1}, [%2];" : "=l"(a), "=l"(b) : "r"(addr));
}
__device__ __forceinline__ ull lds_b64(uint32_t addr) {
    ull a; asm volatile("ld.shared.b64 %0, [%1];" : "=l"(a) : "r"(addr)); return a;
}
__device__ __forceinline__ void cp16(uint32_t dst, const void* src) {
    asm volatile("cp.async.ca.shared.global [%0], [%1], 16;" :: "r"(dst), "l"(src));
}
__device__ __forceinline__ void cp_commit() { asm volatile("cp.async.commit_group;"); }
__device__ __forceinline__ void cp_wait0()  { asm volatile("cp.async.wait_group 0;"); }
__device__ __forceinline__ void cp_wait1()  { asm volatile("cp.async.wait_group 1;"); }

// ================= Stage 1: split-K GEMM  t_ext[U,176] = x @ [W1 | Bp] ==========
// grid (4 u-tiles, 64 k-splits) = 256 blocks (2/SM), block 512 (16 warps).
// 5-stage pipeline of 16 k: W via cp.async double buffer, x via register buffer.
// Warp w owns users w*4..w*4+3. Lane cx owns col-pairs (64c + 2cx, +1), c=0..2.
__global__ void __launch_bounds__(S1_THREADS) stage1_kernel(
    const float* __restrict__ x,
    const float* __restrict__ W1,   // [5120,160]
    const float* __restrict__ Bp)   // [5120,16]
{
    __shared__ __align__(16) ull   xsh[2][S1_KK * XPITCH];    // {x,x} dup, 2x8.4KB
    __shared__ __align__(16) float wsh[2][S1_KK * NPAD];      // [k][col], 2x12.3KB

    const int tid = threadIdx.x;
    const int cx  = tid & 31;
    const int wid = tid >> 5;        // 0..15
    const int u0  = blockIdx.x * S1_UT;
    const int k0  = blockIdx.y * S1_KC;

    const uint32_t xb = (uint32_t)__cvta_generic_to_shared(xsh);
    const uint32_t wb = (uint32_t)__cvta_generic_to_shared(wsh);

    // per-thread x element coordinates: 2 users (stride 32), one k each
    const int xu = tid >> 4;         // 0..31 base user
    const int xk = tid & 15;         // k within stage

    auto stage_w = [&](int s, int b) {
        const int kb = k0 + s * S1_KK;
        const uint32_t wdst = wb + (uint32_t)(b * S1_KK * NPAD) * 4u;
        for (int ch = tid; ch < S1_KK * 40; ch += S1_THREADS) {
            int k = ch / 40, c = ch - k * 40;
            cp16(wdst + (uint32_t)(k * NPAD + c * 4) * 4u,
                 W1 + (size_t)(kb + k) * R_DIM + c * 4);
        }
        if (tid < S1_KK * 4) {
            int k = tid >> 2, c = tid & 3;
            cp16(wdst + (uint32_t)(k * NPAD + R_DIM + c * 4) * 4u,
                 Bp + (size_t)(kb + k) * N_DIM + c * 4);
        }
        cp_commit();
    };
    float xr[2];
    auto load_x = [&](int s) {
#pragma unroll
        for (int j = 0; j < 2; ++j) {
            int u = xu + j * 32;
            xr[j] = x[(size_t)(u0 + u) * D_DIM + k0 + s * S1_KK + xk];
        }
    };
    auto sts_x = [&](int b) {
#pragma unroll
        for (int j = 0; j < 2; ++j)
            xsh[b][xk * XPITCH + xu + j * 32] = pack2(xr[j]);
    };

    ull acc[4][3];
#pragma unroll
    for (int uu = 0; uu < 4; ++uu)
#pragma unroll
        for (int c = 0; c < 3; ++c) acc[uu][c] = 0ULL;

    stage_w(0, 0);
    load_x(0);

#pragma unroll 1
    for (int s = 0; s < S1_NST; ++s) {
        const int b = s & 1;
        sts_x(b);
        if (s + 1 < S1_NST) stage_w(s + 1, 1 - b);
        if (s + 1 < S1_NST) cp_wait1(); else cp_wait0();
        __syncthreads();
        if (s + 1 < S1_NST) load_x(s + 1);

        const uint32_t xbase = xb + (uint32_t)(b * S1_KK * XPITCH) * 8u;
        const uint32_t wbase = wb + (uint32_t)(b * S1_KK * NPAD) * 4u;
#pragma unroll 4
        for (int kk = 0; kk < S1_KK; ++kk) {
            ull xp[4];
            const uint32_t xa = xbase + (uint32_t)(kk * XPITCH + wid * 4) * 8u;
            lds_v2b64(xp[0], xp[1], xa);
            lds_v2b64(xp[2], xp[3], xa + 16u);
            const uint32_t wa = wbase + (uint32_t)(kk * NPAD + 2 * cx) * 4u;
            ull wp[3];
            wp[0] = lds_b64(wa);
            wp[1] = lds_b64(wa + 256u);
            wp[2] = lds_b64(wa + 512u);
#pragma unroll
            for (int c = 0; c < 3; ++c)
#pragma unroll
                for (int uu = 0; uu < 4; ++uu) fma2(acc[uu][c], xp[uu], wp[c]);
        }
        __syncthreads();
    }

    // writeout: packed 8B stores of col-pairs (64c+2cx, +1); pair valid iff c<2 || cx<24
    float* pout = g_partial + (size_t)blockIdx.y * (U_DIM * NCOL);
#pragma unroll
    for (int uu = 0; uu < 4; ++uu) {
        const int u = u0 + wid * 4 + uu;
#pragma unroll
        for (int c = 0; c < 3; ++c) {
            if (c < 2 || cx < 24) {
                const int col = 64 * c + 2 * cx;
                *(ull*)(pout + (size_t)u * NCOL + col) = acc[uu][c];
            }
        }
    }
}

// ================= Stage 2: reduce 64 split partials (float4) ===================
#define RED_F4 (U_DIM * NCOL / 4)   // 11264
__global__ void __launch_bounds__(256) reduce_kernel() {
    const int idx = blockIdx.x * 256 + threadIdx.x;   // 44 * 256 == 11264 exactly
    const float4* p4 = (const float4*)g_partial;
    float4 s = make_float4(0.f, 0.f, 0.f, 0.f);
#pragma unroll 8
    for (int sp = 0; sp < S1_SPLITS; ++sp) {
        float4 v = __ldcg(p4 + (size_t)sp * RED_F4 + idx);
        s.x += v.x; s.y += v.y; s.z += v.z; s.w += v.w;
    }
    ((float4*)g_tbuf)[idx] = s;
}

// ================= Stage 3: fused dt-GEMM + softplus + streaming ================
// (exact R8 winner: FU_UT=8, RCH=16, 2-deep ping-pong, occ 6)
#define FU_UT 8
#define FU_DT 128
#define RCH 16
#define NCH (R_DIM / RCH)      // 10 chunks
#define W2CHUNK (RCH * FU_DT)  // 2048 floats

__global__ void __launch_bounds__(256, 6) fused_kernel(
    const float* __restrict__ W2,    // [160,5120]
    const float* __restrict__ bias,  // [5120]
    const float* __restrict__ x,     // [256,5120]
    const float4* __restrict__ abar4,
    const float4* __restrict__ hst4,
    float4* __restrict__ out4)
{
    __shared__ __align__(16) ull   tpair[R_DIM * 4];          // {t_u,t_u+1} 5.1 KB
    __shared__ __align__(16) float w2sh[2 * W2CHUNK];         // 16 KB ping-pong
    __shared__ __align__(16) float c1sh[FU_UT * FU_DT];       // 4 KB
    __shared__ __align__(16) float Bsh[FU_UT * N_DIM];        // 0.5 KB

    const int u0  = blockIdx.x * FU_UT;
    const int d0  = blockIdx.y * FU_DT;
    const int tid = threadIdx.x;

    const uint32_t w2b = (uint32_t)__cvta_generic_to_shared(w2sh);
    const uint32_t tpb = (uint32_t)__cvta_generic_to_shared(tpair);

    {
#pragma unroll
        for (int q = 0; q < 2; ++q) {
            int ch = tid + q * 256;
            int row = ch >> 5, c = ch & 31;
            cp16(w2b + (uint32_t)(row * FU_DT + c * 4) * 4u,
                 W2 + (size_t)row * D_DIM + d0 + c * 4);
        }
    }
    cp_commit();

    for (int e = tid; e < R_DIM * 4; e += 256) {
        int r = e >> 2, p = e & 3;
        float lo = g_tbuf[(size_t)(u0 + 2 * p)     * NCOL + r];
        float hi = g_tbuf[(size_t)(u0 + 2 * p + 1) * NCOL + r];
        tpair[r * 4 + p] = combine2(lo, hi);
    }
    if (tid < FU_UT * N_DIM) {
        int u = tid >> 4, n = tid & 15;
        Bsh[tid] = g_tbuf[(size_t)(u0 + u) * NCOL + R_DIM + n];
    }

    const int dl = tid & 127;
    const int g  = tid >> 7;       // 0 or 1
    const int pg = g * 2;          // pair-group base
    const int d  = d0 + dl;

    ull acc[2];
    acc[0] = 0ULL; acc[1] = 0ULL;

#pragma unroll 1
    for (int s = 0; s < NCH; ++s) {
        cp_wait0();
        __syncthreads();
        if (s + 1 < NCH) {
#pragma unroll
            for (int q = 0; q < 2; ++q) {
                int ch = tid + q * 256;
                int row = ch >> 5, c = ch & 31;
                cp16(w2b + (uint32_t)(((s + 1) & 1) * W2CHUNK + row * FU_DT + c * 4) * 4u,
                     W2 + (size_t)((s + 1) * RCH + row) * D_DIM + d0 + c * 4);
            }
            cp_commit();
        }
        const uint32_t wbase = w2b + (uint32_t)((s & 1) * W2CHUNK + dl) * 4u;
        const uint32_t tbase = tpb + (uint32_t)(s * RCH * 4 + pg) * 8u;
#pragma unroll
        for (int rr = 0; rr < RCH; ++rr) {
            float wv;
            asm volatile("ld.shared.b32 %0, [%1];"
                         : "=f"(wv) : "r"(wbase + (uint32_t)(rr * FU_DT) * 4u));
            const ull w2 = pack2(wv);
            ull p0, p1;
            lds_v2b64(p0, p1, tbase + (uint32_t)(rr * 4) * 8u);
            fma2(acc[0], p0, w2);
            fma2(acc[1], p1, w2);
        }
    }

    const float bz = bias[d];
    const int ug = g * 4;
#pragma unroll
    for (int i = 0; i < 2; ++i) {
        float z0, z1;
        asm("mov.b64 {%0, %1}, %2;" : "=f"(z0), "=f"(z1) : "l"(acc[i]));
        const int u = ug + 2 * i;
        z0 += bz; z1 += bz;
        const float dt0 = fmaxf(z0, 0.f) + log1pf(expf(-fabsf(z0)));
        const float dt1 = fmaxf(z1, 0.f) + log1pf(expf(-fabsf(z1)));
        c1sh[u * FU_DT + dl]       = dt0 * __ldg(x + (size_t)(u0 + u) * D_DIM + d);
        c1sh[(u + 1) * FU_DT + dl] = dt1 * __ldg(x + (size_t)(u0 + u + 1) * D_DIM + d);
    }
    __syncthreads();

    const int n4 = tid & 3;
    const int i0 = tid;
    const int i1 = tid + 256;

#pragma unroll 2
    for (int u = 0; u < FU_UT; ++u) {
        const size_t base = ((size_t)(u0 + u) * D_DIM + d0) * 4;
        const float4 b = *(const float4*)(Bsh + u * N_DIM + n4 * 4);
        const float c0 = c1sh[u * FU_DT + (i0 >> 2)];
        const float c1 = c1sh[u * FU_DT + (i1 >> 2)];

        const float4 a0 = __ldcs(abar4 + base + i0);
        const float4 h0 = __ldcs(hst4  + base + i0);
        const float4 a1 = __ldcs(abar4 + base + i1);
        const float4 h1 = __ldcs(hst4  + base + i1);

        float4 o0, o1;
        o0.x = fmaf(a0.x, h0.x, c0 * b.x);
        o0.y = fmaf(a0.y, h0.y, c0 * b.y);
        o0.z = fmaf(a0.z, h0.z, c0 * b.z);
        o0.w = fmaf(a0.w, h0.w, c0 * b.w);
        o1.x = fmaf(a1.x, h1.x, c1 * b.x);
        o1.y = fmaf(a1.y, h1.y, c1 * b.y);
        o1.z = fmaf(a1.z, h1.z, c1 * b.z);
        o1.w = fmaf(a1.w, h1.w, c1 * b.w);
        __stcs(out4 + base + i0, o0);
        __stcs(out4 + base + i1, o1);
    }
}

extern "C" void kernel_launch(void* const* d_in, const int* in_sizes, int n_in,
                              void* d_out, int out_size) {
    const float* x    = (const float*)d_in[0];   // [256,5120]
    const float* W1   = (const float*)d_in[1];   // [5120,160]
    const float* W2   = (const float*)d_in[2];   // [160,5120]
    const float* bias = (const float*)d_in[3];   // [5120]
    const float* Bp   = (const float*)d_in[4];   // [5120,16]
    const float* abar = (const float*)d_in[5];   // [256,5120,16]
    const float* hst  = (const float*)d_in[6];   // [256,5120,16]
    float* out = (float*)d_out;

    stage1_kernel<<<dim3(U_DIM / S1_UT, S1_SPLITS), S1_THREADS>>>(x, W1, Bp);
    reduce_kernel<<<RED_F4 / 256, 256>>>();
    fused_kernel<<<dim3(U_DIM / FU_UT, D_DIM / FU_DT), 256>>>(
        W2, bias, x, (const float4*)abar, (const float4*)hst, (float4*)out);
}